// round 10
// baseline (speedup 1.0000x reference)
#include <cuda_runtime.h>
#include <math.h>

#define NB 4096
#define NS 64
#define NY 256
#define NH 128
#define NE 32
#define NKG 8
#define NKA 20
#define NNC 50
#define NNT 5

typedef unsigned long long ull;

__device__ __forceinline__ float sigmoidf_(float v) { return 1.f / (1.f + expf(-v)); }

#define FMA2(acc, a, b) asm("fma.rn.f32x2 %0, %1, %2, %0;" : "+l"(acc) : "l"(a), "l"(b))
#define PACK2(o, lo, hi) asm("mov.b64 %0, {%1, %2};" : "=l"(o) : "f"(lo), "f"(hi))
#define UNPACK2(lo, hi, in) asm("mov.b64 {%0, %1}, %2;" : "=f"(lo), "=f"(hi) : "l"(in))
#define FMAX4(m, v) do { \
    m.x = fmaxf(m.x, v.x); m.y = fmaxf(m.y, v.y); \
    m.z = fmaxf(m.z, v.z); m.w = fmaxf(m.w, v.w); } while (0)

#define NBAR_SYNC(id, cnt)   asm volatile("bar.sync %0, %1;"   :: "r"(id), "r"(cnt) : "memory")
#define NBAR_ARRIVE(id, cnt) asm volatile("bar.arrive %0, %1;" :: "r"(id), "r"(cnt) : "memory")

// one 4-K step of a 4-row column GEMM, f32x2
#define GSTEP(W, STRIDE, CC, XB, RS, I, ACC) do {                               \
    float _w0 = (W)[((I) + 0) * (STRIDE) + (CC)];                               \
    float _w1 = (W)[((I) + 1) * (STRIDE) + (CC)];                               \
    float _w2 = (W)[((I) + 2) * (STRIDE) + (CC)];                               \
    float _w3 = (W)[((I) + 3) * (STRIDE) + (CC)];                               \
    ull _wa, _wb; PACK2(_wa, _w0, _w1); PACK2(_wb, _w2, _w3);                   \
    _Pragma("unroll")                                                           \
    for (int _j = 0; _j < 4; _j++) {                                            \
        ulonglong2 _x = *reinterpret_cast<const ulonglong2*>(                   \
            &(XB)[_j * (RS) + (I)]);                                            \
        FMA2((ACC)[_j], _x.x, _wa);                                             \
        FMA2((ACC)[_j], _x.y, _wb);                                             \
    } } while (0)

__device__ __forceinline__ void head_sel(int c,
    const float* W_country, const float* W_type, const float* W_taste,
    const float* W_grape, const float* W_aroma,
    const float** Wp, int* stride, int* cc)
{
    if (c < NNC)       { *Wp = W_country; *stride = NNC; *cc = c; }
    else if (c == NNC) { *Wp = W_type;    *stride = 1;   *cc = 0; }
    else if (c < 56)   { *Wp = W_taste;   *stride = NNT; *cc = c - 51; }
    else if (c < 88)   { *Wp = W_grape;   *stride = NE;  *cc = c - 56; }
    else if (c < 120)  { *Wp = W_aroma;   *stride = NE;  *cc = c - 88; }
    else               { *Wp = W_country; *stride = NNC; *cc = 0; }   // dummy lanes
}

// Warp-specialized: 8 rows/block in 2 groups of 4; warps 0-3 stream, warps 4-7 compute.
__global__ __launch_bounds__(256, 4) void wine_ws(
    const float4* __restrict__ x4,
    const int*   __restrict__ grapes,
    const float* __restrict__ grapes_scales,
    const int*   __restrict__ aromas,
    const float* __restrict__ aromas_scales,
    const float* __restrict__ W_common, const float* __restrict__ b_common,
    const float* __restrict__ W_country, const float* __restrict__ b_country,
    const float* __restrict__ W_type,   const float* __restrict__ b_type,
    const float* __restrict__ W_taste,  const float* __restrict__ b_taste,
    const float* __restrict__ W_aroma,  const float* __restrict__ b_aroma,
    const float* __restrict__ W_grape,  const float* __restrict__ b_grape,
    const float* __restrict__ grapes_emb,
    const float* __restrict__ aroma_emb,
    float* __restrict__ out)
{
    __shared__ __align__(16) float xs[2][4 * NY];   // 8 KB ping-pong (group 0 / group 1)
    __shared__ __align__(16) float ys[4 * NH];      // 2 KB
    __shared__ __align__(16) float yg_sm[8 * NE];   // 1 KB
    __shared__ __align__(16) float ya_sm[8 * NE];   // 1 KB

    const int tid = threadIdx.x;
    const int b0  = blockIdx.x * 8;

    if (tid < 128) {
        // =========================== PRODUCER: stream ===========================
        const int ptid = tid;
        const int pr0  = ptid >> 6;        // 0..1
        const int pr1  = pr0 + 2;          // 2..3
        const int pc   = ptid & 63;

        #pragma unroll
        for (int g = 0; g < 2; g++) {
            const float4* p0 = x4 + (size_t)(b0 + 4 * g + pr0) * (NS * NY / 4) + pc;
            const float4* p1 = x4 + (size_t)(b0 + 4 * g + pr1) * (NS * NY / 4) + pc;
            float4 a0 = p0[0], a1 = p0[64];
            float4 c0 = p1[0], c1 = p1[64];
            {
                float4 u2 = p0[128], u3 = p0[192];
                float4 w2 = p1[128], w3 = p1[192];
                FMAX4(a0, u2); FMAX4(a1, u3);
                FMAX4(c0, w2); FMAX4(c1, w3);
            }
            #pragma unroll
            for (int s = 4; s < NS; s += 4) {
                float4 u0 = p0[(s + 0) * 64], u1 = p0[(s + 1) * 64];
                float4 u2 = p0[(s + 2) * 64], u3 = p0[(s + 3) * 64];
                float4 w0 = p1[(s + 0) * 64], w1 = p1[(s + 1) * 64];
                float4 w2 = p1[(s + 2) * 64], w3 = p1[(s + 3) * 64];
                FMAX4(a0, u0); FMAX4(a1, u1); FMAX4(a0, u2); FMAX4(a1, u3);
                FMAX4(c0, w0); FMAX4(c1, w1); FMAX4(c0, w2); FMAX4(c1, w3);
            }
            float4 ra, rc;
            ra.x = fmaxf(a0.x, a1.x); ra.y = fmaxf(a0.y, a1.y);
            ra.z = fmaxf(a0.z, a1.z); ra.w = fmaxf(a0.w, a1.w);
            rc.x = fmaxf(c0.x, c1.x); rc.y = fmaxf(c0.y, c1.y);
            rc.z = fmaxf(c0.z, c1.z); rc.w = fmaxf(c0.w, c1.w);
            reinterpret_cast<float4*>(xs[g])[pr0 * (NY / 4) + pc] = ra;
            reinterpret_cast<float4*>(xs[g])[pr1 * (NY / 4) + pc] = rc;
            NBAR_ARRIVE(1 + g, 256);
        }

        // producers also write the "true" outputs (independent of compute)
        if (ptid < 64) {
            const int r = ptid >> 3, k = ptid & 7;
            out[(size_t)NB * 64 + (size_t)(b0 + r) * NKG + k] =
                grapes_scales[(b0 + r) * NKG + k];
        }
        for (int task = ptid; task < 8 * NKA; task += 128) {
            const int r = task / NKA, k = task % NKA;
            out[(size_t)NB * 92 + (size_t)(b0 + r) * NKA + k] =
                aromas_scales[(b0 + r) * NKA + k];
        }
    } else {
        // =========================== CONSUMER: compute ===========================
        const int h = tid - 128;            // 0..127 (output column)
        const float* Wp; int hstride, hcc;
        head_sel(h, W_country, W_type, W_taste, W_grape, W_aroma, &Wp, &hstride, &hcc);
        const float bcm = b_common[h];

        #pragma unroll
        for (int g = 0; g < 2; g++) {
            NBAR_SYNC(1 + g, 256);          // wait xs[g]

            // GEMM1: full K=256, direct accumulation (no split-K)
            ull acc[4] = {0ull, 0ull, 0ull, 0ull};
            #pragma unroll 4
            for (int it = 0; it < 64; it++)
                GSTEP(W_common, NH, h, xs[g], NY, 4 * it, acc);
            #pragma unroll
            for (int j = 0; j < 4; j++) {
                float lo, hi; UNPACK2(lo, hi, acc[j]);
                float v = lo + hi + bcm;
                ys[j * NH + h] = (v > 0.f) ? v : expm1f(v);
            }
            NBAR_SYNC(7, 128);              // ys ready

            // heads: K=128, direct accumulation
            ull acch[4] = {0ull, 0ull, 0ull, 0ull};
            #pragma unroll 4
            for (int it = 0; it < 32; it++)
                GSTEP(Wp, hstride, hcc, ys, NH, 4 * it, acch);

            const int gb = b0 + 4 * g;
            float s_[4];
            #pragma unroll
            for (int j = 0; j < 4; j++) {
                float lo, hi; UNPACK2(lo, hi, acch[j]);
                s_[j] = lo + hi;
            }
            if (h < NNC) {
                float bb = b_country[h];
                #pragma unroll
                for (int j = 0; j < 4; j++)
                    out[(size_t)(gb + j) * NNC + h] = s_[j] + bb;
            } else if (h == NNC) {
                float bb = b_type[0];
                #pragma unroll
                for (int j = 0; j < 4; j++)
                    out[(size_t)NB * NNC + (gb + j)] = sigmoidf_(s_[j] + bb);
            } else if (h < 56) {
                const int cc = h - 51;
                float bb = b_taste[cc];
                #pragma unroll
                for (int j = 0; j < 4; j++)
                    out[(size_t)NB * 51 + (size_t)(gb + j) * NNT + cc] = sigmoidf_(s_[j] + bb);
            } else if (h < 88) {
                const int e = h - 56;
                float bb = b_grape[e];
                #pragma unroll
                for (int j = 0; j < 4; j++) yg_sm[(4 * g + j) * NE + e] = s_[j] + bb;
            } else if (h < 120) {
                const int e = h - 88;
                float bb = b_aroma[e];
                #pragma unroll
                for (int j = 0; j < 4; j++) ya_sm[(4 * g + j) * NE + e] = s_[j] + bb;
            }
            NBAR_SYNC(7, 128);              // ys WAR protection / yg,ya ready after g1
        }

        // ragged preds for all 8 rows (128 consumer threads)
        if (h < 64) {
            const int r = h >> 3, k = h & 7;
            const int b = b0 + r;
            const int idx = grapes[b * NKG + k];
            const float4* emb = reinterpret_cast<const float4*>(grapes_emb) + (size_t)idx * (NE / 4);
            const float4* yv4 = reinterpret_cast<const float4*>(&yg_sm[r * NE]);
            float acc = 0.f;
            #pragma unroll
            for (int i = 0; i < NE / 4; i++) {
                float4 ev = emb[i], yv = yv4[i];
                acc += ev.x * yv.x + ev.y * yv.y + ev.z * yv.z + ev.w * yv.w;
            }
            float mask = (idx != 0) ? 1.f : 0.f;
            out[(size_t)NB * 56 + (size_t)b * NKG + k] = sigmoidf_(acc) * mask;
        }
        for (int task = h; task < 8 * NKA; task += 128) {
            const int r = task / NKA, k = task % NKA;
            const int b = b0 + r;
            const int idx = aromas[b * NKA + k];
            const float sc2 = aromas_scales[b * NKA + k];
            const float4* emb = reinterpret_cast<const float4*>(aroma_emb) + (size_t)idx * (NE / 4);
            const float4* yv4 = reinterpret_cast<const float4*>(&ya_sm[r * NE]);
            float acc = 0.f;
            #pragma unroll
            for (int i = 0; i < NE / 4; i++) {
                float4 ev = emb[i], yv = yv4[i];
                acc += ev.x * yv.x + ev.y * yv.y + ev.z * yv.z + ev.w * yv.w;
            }
            float mask = (sc2 != 0.f) ? 1.f : 0.f;
            out[(size_t)NB * 72 + (size_t)b * NKA + k] = sigmoidf_(acc) * mask;
        }
    }
}

extern "C" void kernel_launch(void* const* d_in, const int* in_sizes, int n_in,
                              void* d_out, int out_size) {
    const float* x_enc          = (const float*)d_in[0];
    const int*   grapes         = (const int*)  d_in[1];
    const float* grapes_scales  = (const float*)d_in[2];
    const int*   aromas         = (const int*)  d_in[3];
    const float* aromas_scales  = (const float*)d_in[4];
    const float* W_common       = (const float*)d_in[5];
    const float* b_common       = (const float*)d_in[6];
    const float* W_country      = (const float*)d_in[7];
    const float* b_country      = (const float*)d_in[8];
    const float* W_type         = (const float*)d_in[9];
    const float* b_type         = (const float*)d_in[10];
    const float* W_taste        = (const float*)d_in[11];
    const float* b_taste        = (const float*)d_in[12];
    const float* W_aroma        = (const float*)d_in[13];
    const float* b_aroma        = (const float*)d_in[14];
    const float* W_grape        = (const float*)d_in[15];
    const float* b_grape        = (const float*)d_in[16];
    const float* grapes_emb     = (const float*)d_in[17];
    const float* aroma_emb      = (const float*)d_in[18];
    float* out = (float*)d_out;

    wine_ws<<<NB / 8, 256>>>(reinterpret_cast<const float4*>(x_enc),
                             grapes, grapes_scales, aromas, aromas_scales,
                             W_common, b_common, W_country, b_country,
                             W_type, b_type, W_taste, b_taste,
                             W_aroma, b_aroma, W_grape, b_grape,
                             grapes_emb, aroma_emb, out);
}

// round 11
// speedup vs baseline: 1.3316x; 1.3316x over previous
#include <cuda_runtime.h>
#include <math.h>

#define NB 4096
#define NS 64
#define NY 256
#define NH 128
#define NE 32
#define NKG 8
#define NKA 20
#define NNC 50
#define NNT 5

typedef unsigned long long ull;

__device__ __forceinline__ float sigmoidf_(float v) { return 1.f / (1.f + expf(-v)); }

#define FMA2(acc, a, b) asm("fma.rn.f32x2 %0, %1, %2, %0;" : "+l"(acc) : "l"(a), "l"(b))
#define PACK2(o, lo, hi) asm("mov.b64 %0, {%1, %2};" : "=l"(o) : "f"(lo), "f"(hi))
#define UNPACK2(lo, hi, in) asm("mov.b64 {%0, %1}, %2;" : "=f"(lo), "=f"(hi) : "l"(in))
#define FMAX4(m, v) do { \
    m.x = fmaxf(m.x, v.x); m.y = fmaxf(m.y, v.y); \
    m.z = fmaxf(m.z, v.z); m.w = fmaxf(m.w, v.w); } while (0)

// one 4-K step of a 4-row column GEMM, f32x2 (XB pre-offset to this thread's row base)
#define GSTEP(W, STRIDE, CC, XB, RS, I, ACC) do {                               \
    float _w0 = (W)[((I) + 0) * (STRIDE) + (CC)];                               \
    float _w1 = (W)[((I) + 1) * (STRIDE) + (CC)];                               \
    float _w2 = (W)[((I) + 2) * (STRIDE) + (CC)];                               \
    float _w3 = (W)[((I) + 3) * (STRIDE) + (CC)];                               \
    ull _wa, _wb; PACK2(_wa, _w0, _w1); PACK2(_wb, _w2, _w3);                   \
    _Pragma("unroll")                                                           \
    for (int _j = 0; _j < 4; _j++) {                                            \
        ulonglong2 _x = *reinterpret_cast<const ulonglong2*>(                   \
            &(XB)[_j * (RS) + (I)]);                                            \
        FMA2((ACC)[_j], _x.x, _wa);                                             \
        FMA2((ACC)[_j], _x.y, _wb);                                             \
    } } while (0)

__device__ __forceinline__ void head_sel(int c,
    const float* W_country, const float* W_type, const float* W_taste,
    const float* W_grape, const float* W_aroma,
    const float** Wp, int* stride, int* cc)
{
    if (c < NNC)       { *Wp = W_country; *stride = NNC; *cc = c; }
    else if (c == NNC) { *Wp = W_type;    *stride = 1;   *cc = 0; }
    else if (c < 56)   { *Wp = W_taste;   *stride = NNT; *cc = c - 51; }
    else if (c < 88)   { *Wp = W_grape;   *stride = NE;  *cc = c - 56; }
    else if (c < 120)  { *Wp = W_aroma;   *stride = NE;  *cc = c - 88; }
    else               { *Wp = W_country; *stride = NNC; *cc = 0; }   // dummy lanes
}

// 8 rows/block; column-split pipelined stream+GEMM; 256 threads; grid 512; single wave.
__global__ __launch_bounds__(256, 4) void wine_cs(
    const float4* __restrict__ x4,
    const int*   __restrict__ grapes,
    const float* __restrict__ grapes_scales,
    const int*   __restrict__ aromas,
    const float* __restrict__ aromas_scales,
    const float* __restrict__ W_common, const float* __restrict__ b_common,
    const float* __restrict__ W_country, const float* __restrict__ b_country,
    const float* __restrict__ W_type,   const float* __restrict__ b_type,
    const float* __restrict__ W_taste,  const float* __restrict__ b_taste,
    const float* __restrict__ W_aroma,  const float* __restrict__ b_aroma,
    const float* __restrict__ W_grape,  const float* __restrict__ b_grape,
    const float* __restrict__ grapes_emb,
    const float* __restrict__ aroma_emb,
    float* __restrict__ out)
{
    __shared__ __align__(16) float x_sm[8 * NY];    // 8 KB
    __shared__ __align__(16) float ys[8 * NH];      // 4 KB
    __shared__ __align__(16) float yg_sm[8 * NE];   // 1 KB
    __shared__ __align__(16) float ya_sm[8 * NE];   // 1 KB

    const int tid  = threadIdx.x;
    const int b0   = blockIdx.x * 8;
    const int h    = tid & 127;          // output column
    const int half = tid >> 7;           // row half: rows 4*half..4*half+3
    const int sr   = tid >> 5;           // stream row 0..7
    const int sc   = tid & 31;           // stream float4-col within half (0..31)

    // ---------- hoisted ragged indices/scales + "true" outputs ----------
    int g_idx = 0; float a_sc = 0.f; int a_idx = 0;
    if (tid < 64) {
        const int r = tid >> 3, k = tid & 7;
        g_idx = grapes[(b0 + r) * NKG + k];
        out[(size_t)NB * 64 + (size_t)(b0 + r) * NKG + k] =
            grapes_scales[(b0 + r) * NKG + k];
    } else if (tid < 224) {
        const int task = tid - 64;
        const int r = task / NKA, k = task % NKA;
        a_idx = aromas[(b0 + r) * NKA + k];
        a_sc  = aromas_scales[(b0 + r) * NKA + k];
        out[(size_t)NB * 92 + (size_t)(b0 + r) * NKA + k] = a_sc;
    }

    // ================ P1: stream columns [0,128) of all 8 rows ================
    {
        const float4* p = x4 + (size_t)(b0 + sr) * (NS * NY / 4) + sc;
        float4 m0 = p[0], m1 = p[64], m2 = p[128], m3 = p[192];
        #pragma unroll
        for (int s = 4; s < NS; s += 4) {
            float4 v0 = p[(s + 0) * 64], v1 = p[(s + 1) * 64];
            float4 v2 = p[(s + 2) * 64], v3 = p[(s + 3) * 64];
            FMAX4(m0, v0); FMAX4(m1, v1); FMAX4(m2, v2); FMAX4(m3, v3);
        }
        float4 rr;
        rr.x = fmaxf(fmaxf(m0.x, m1.x), fmaxf(m2.x, m3.x));
        rr.y = fmaxf(fmaxf(m0.y, m1.y), fmaxf(m2.y, m3.y));
        rr.z = fmaxf(fmaxf(m0.z, m1.z), fmaxf(m2.z, m3.z));
        rr.w = fmaxf(fmaxf(m0.w, m1.w), fmaxf(m2.w, m3.w));
        reinterpret_cast<float4*>(x_sm)[sr * (NY / 4) + sc] = rr;
    }
    __syncthreads();

    ull acc[4] = {0ull, 0ull, 0ull, 0ull};          // GEMM1 accs, live across P2/P3
    const float* xbase = &x_sm[4 * half * NY];

    // ===== P2: GEMM1 K[0:128) interleaved with stream of columns [128,256) =====
    {
        const float4* p = x4 + (size_t)(b0 + sr) * (NS * NY / 4) + 32 + sc;
        float4 m0 = p[0], m1 = p[64];
        #pragma unroll 4
        for (int it = 0; it < 31; it++) {
            float4 v0 = p[(2 * it + 2) * 64];
            float4 v1 = p[(2 * it + 3) * 64];
            GSTEP(W_common, NH, h, xbase, NY, 4 * it, acc);
            FMAX4(m0, v0); FMAX4(m1, v1);
        }
        GSTEP(W_common, NH, h, xbase, NY, 124, acc);
        float4 rr;
        rr.x = fmaxf(m0.x, m1.x); rr.y = fmaxf(m0.y, m1.y);
        rr.z = fmaxf(m0.z, m1.z); rr.w = fmaxf(m0.w, m1.w);
        reinterpret_cast<float4*>(x_sm)[sr * (NY / 4) + 32 + sc] = rr;
    }
    __syncthreads();

    // ================= P3: GEMM1 K[128:256), then y = elu(.) =================
    {
        #pragma unroll 4
        for (int it = 32; it < 64; it++)
            GSTEP(W_common, NH, h, xbase, NY, 4 * it, acc);
        const float bcm = b_common[h];
        #pragma unroll
        for (int j = 0; j < 4; j++) {
            float lo, hi; UNPACK2(lo, hi, acc[j]);
            float v = lo + hi + bcm;
            ys[(4 * half + j) * NH + h] = (v > 0.f) ? v : expm1f(v);
        }
    }
    __syncthreads();

    // ========================= P4: heads (full K=128) =========================
    {
        const float* Wp; int hstride, hcc;
        head_sel(h, W_country, W_type, W_taste, W_grape, W_aroma, &Wp, &hstride, &hcc);
        const float* ybase = &ys[4 * half * NH];
        ull acch[4] = {0ull, 0ull, 0ull, 0ull};
        #pragma unroll 4
        for (int it = 0; it < 32; it++)
            GSTEP(Wp, hstride, hcc, ybase, NH, 4 * it, acch);

        const int gb = b0 + 4 * half;
        float s_[4];
        #pragma unroll
        for (int j = 0; j < 4; j++) {
            float lo, hi; UNPACK2(lo, hi, acch[j]);
            s_[j] = lo + hi;
        }
        if (h < NNC) {
            float bb = b_country[h];
            #pragma unroll
            for (int j = 0; j < 4; j++)
                out[(size_t)(gb + j) * NNC + h] = s_[j] + bb;
        } else if (h == NNC) {
            float bb = b_type[0];
            #pragma unroll
            for (int j = 0; j < 4; j++)
                out[(size_t)NB * NNC + (gb + j)] = sigmoidf_(s_[j] + bb);
        } else if (h < 56) {
            const int cc = h - 51;
            float bb = b_taste[cc];
            #pragma unroll
            for (int j = 0; j < 4; j++)
                out[(size_t)NB * 51 + (size_t)(gb + j) * NNT + cc] = sigmoidf_(s_[j] + bb);
        } else if (h < 88) {
            const int e = h - 56;
            float bb = b_grape[e];
            #pragma unroll
            for (int j = 0; j < 4; j++) yg_sm[(4 * half + j) * NE + e] = s_[j] + bb;
        } else if (h < 120) {
            const int e = h - 88;
            float bb = b_aroma[e];
            #pragma unroll
            for (int j = 0; j < 4; j++) ya_sm[(4 * half + j) * NE + e] = s_[j] + bb;
        }
    }
    __syncthreads();

    // ========================= P5: ragged predictions =========================
    if (tid < 64) {                           // 8 rows x 8 grape slots
        const int r = tid >> 3, k = tid & 7;
        const int b = b0 + r;
        const float4* emb = reinterpret_cast<const float4*>(grapes_emb) + (size_t)g_idx * (NE / 4);
        const float4* yv4 = reinterpret_cast<const float4*>(&yg_sm[r * NE]);
        float acc2 = 0.f;
        #pragma unroll
        for (int i = 0; i < NE / 4; i++) {
            float4 ev = emb[i], yv = yv4[i];
            acc2 += ev.x * yv.x + ev.y * yv.y + ev.z * yv.z + ev.w * yv.w;
        }
        float mask = (g_idx != 0) ? 1.f : 0.f;
        out[(size_t)NB * 56 + (size_t)b * NKG + k] = sigmoidf_(acc2) * mask;
    } else if (tid < 224) {                   // 8 rows x 20 aroma slots
        const int task = tid - 64;
        const int r = task / NKA, k = task % NKA;
        const int b = b0 + r;
        const float4* emb = reinterpret_cast<const float4*>(aroma_emb) + (size_t)a_idx * (NE / 4);
        const float4* yv4 = reinterpret_cast<const float4*>(&ya_sm[r * NE]);
        float acc2 = 0.f;
        #pragma unroll
        for (int i = 0; i < NE / 4; i++) {
            float4 ev = emb[i], yv = yv4[i];
            acc2 += ev.x * yv.x + ev.y * yv.y + ev.z * yv.z + ev.w * yv.w;
        }
        float mask = (a_sc != 0.f) ? 1.f : 0.f;
        out[(size_t)NB * 72 + (size_t)b * NKA + k] = sigmoidf_(acc2) * mask;
    }
}

extern "C" void kernel_launch(void* const* d_in, const int* in_sizes, int n_in,
                              void* d_out, int out_size) {
    const float* x_enc          = (const float*)d_in[0];
    const int*   grapes         = (const int*)  d_in[1];
    const float* grapes_scales  = (const float*)d_in[2];
    const int*   aromas         = (const int*)  d_in[3];
    const float* aromas_scales  = (const float*)d_in[4];
    const float* W_common       = (const float*)d_in[5];
    const float* b_common       = (const float*)d_in[6];
    const float* W_country      = (const float*)d_in[7];
    const float* b_country      = (const float*)d_in[8];
    const float* W_type         = (const float*)d_in[9];
    const float* b_type         = (const float*)d_in[10];
    const float* W_taste        = (const float*)d_in[11];
    const float* b_taste        = (const float*)d_in[12];
    const float* W_aroma        = (const float*)d_in[13];
    const float* b_aroma        = (const float*)d_in[14];
    const float* W_grape        = (const float*)d_in[15];
    const float* b_grape        = (const float*)d_in[16];
    const float* grapes_emb     = (const float*)d_in[17];
    const float* aroma_emb      = (const float*)d_in[18];
    float* out = (float*)d_out;

    wine_cs<<<NB / 8, 256>>>(reinterpret_cast<const float4*>(x_enc),
                             grapes, grapes_scales, aromas, aromas_scales,
                             W_common, b_common, W_country, b_country,
                             W_type, b_type, W_taste, b_taste,
                             W_aroma, b_aroma, W_grape, b_grape,
                             grapes_emb, aroma_emb, out);
}

// round 12
// speedup vs baseline: 1.3691x; 1.0282x over previous
#include <cuda_runtime.h>
#include <math.h>

#define NB 4096
#define NS 64
#define NY 256
#define NH 128
#define NE 32
#define NKG 8
#define NKA 20
#define NNC 50
#define NNT 5
#define SEQROW (NS * NY / 4)   // float4s per batch row

typedef unsigned long long ull;

__device__ __forceinline__ float sigmoidf_(float v) { return 1.f / (1.f + expf(-v)); }

#define FMA2(acc, a, b) asm("fma.rn.f32x2 %0, %1, %2, %0;" : "+l"(acc) : "l"(a), "l"(b))
#define PACK2(o, lo, hi) asm("mov.b64 %0, {%1, %2};" : "=l"(o) : "f"(lo), "f"(hi))
#define UNPACK2(lo, hi, in) asm("mov.b64 {%0, %1}, %2;" : "=f"(lo), "=f"(hi) : "l"(in))
#define FMAX4(m, v) do { \
    m.x = fmaxf(m.x, v.x); m.y = fmaxf(m.y, v.y); \
    m.z = fmaxf(m.z, v.z); m.w = fmaxf(m.w, v.w); } while (0)

// one 4-K step of a 4-row column GEMM, f32x2 (XB pre-offset to this thread's rows)
#define GSTEP(W, STRIDE, CC, XB, RS, I, ACC) do {                               \
    float _w0 = (W)[((I) + 0) * (STRIDE) + (CC)];                               \
    float _w1 = (W)[((I) + 1) * (STRIDE) + (CC)];                               \
    float _w2 = (W)[((I) + 2) * (STRIDE) + (CC)];                               \
    float _w3 = (W)[((I) + 3) * (STRIDE) + (CC)];                               \
    ull _wa, _wb; PACK2(_wa, _w0, _w1); PACK2(_wb, _w2, _w3);                   \
    _Pragma("unroll")                                                           \
    for (int _j = 0; _j < 4; _j++) {                                            \
        ulonglong2 _x = *reinterpret_cast<const ulonglong2*>(                   \
            &(XB)[_j * (RS) + (I)]);                                            \
        FMA2((ACC)[_j], _x.x, _wa);                                             \
        FMA2((ACC)[_j], _x.y, _wb);                                             \
    } } while (0)

__device__ __forceinline__ void head_sel(int c,
    const float* W_country, const float* W_type, const float* W_taste,
    const float* W_grape, const float* W_aroma,
    const float** Wp, int* stride, int* cc)
{
    if (c < NNC)       { *Wp = W_country; *stride = NNC; *cc = c; }
    else if (c == NNC) { *Wp = W_type;    *stride = 1;   *cc = 0; }
    else if (c < 56)   { *Wp = W_taste;   *stride = NNT; *cc = c - 51; }
    else if (c < 88)   { *Wp = W_grape;   *stride = NE;  *cc = c - 56; }
    else if (c < 120)  { *Wp = W_aroma;   *stride = NE;  *cc = c - 88; }
    else               { *Wp = W_country; *stride = NNC; *cc = 0; }   // dummy lanes
}

// 16 rows/block = 2 column-split pipelined tiles of 8; 256 threads; grid 256.
__global__ __launch_bounds__(256, 2) void wine_p2(
    const float4* __restrict__ x4,
    const int*   __restrict__ grapes,
    const float* __restrict__ grapes_scales,
    const int*   __restrict__ aromas,
    const float* __restrict__ aromas_scales,
    const float* __restrict__ W_common, const float* __restrict__ b_common,
    const float* __restrict__ W_country, const float* __restrict__ b_country,
    const float* __restrict__ W_type,   const float* __restrict__ b_type,
    const float* __restrict__ W_taste,  const float* __restrict__ b_taste,
    const float* __restrict__ W_aroma,  const float* __restrict__ b_aroma,
    const float* __restrict__ W_grape,  const float* __restrict__ b_grape,
    const float* __restrict__ grapes_emb,
    const float* __restrict__ aroma_emb,
    float* __restrict__ out)
{
    __shared__ __align__(16) float xs[2][8 * NY];   // 16 KB (tile 0 / tile 1)
    __shared__ __align__(16) float ys[8 * NH];      // 4 KB (reused per tile)
    __shared__ __align__(16) float yg_sm[8 * NE];   // 1 KB (reused per tile)
    __shared__ __align__(16) float ya_sm[8 * NE];   // 1 KB

    const int tid  = threadIdx.x;
    const int b0   = blockIdx.x * 16;
    const int h    = tid & 127;          // output column
    const int half = tid >> 7;           // GEMM rows 4*half..4*half+3 of the tile
    const int sr   = tid >> 5;           // stream row 0..7
    const int sc   = tid & 31;           // stream float4-col within half (0..31)

    const float* Wp; int hstride, hcc;
    head_sel(h, W_country, W_type, W_taste, W_grape, W_aroma, &Wp, &hstride, &hcc);

    // ---------- hoisted ragged indices (both tiles) + "true" outputs ----------
    int gi0 = 0, gi1 = 0, ai0 = 0, ai1 = 0;
    float as0 = 0.f, as1 = 0.f;
    if (tid < 64) {
        const int r = tid >> 3, k = tid & 7;
        gi0 = grapes[(b0 + r) * NKG + k];
        gi1 = grapes[(b0 + 8 + r) * NKG + k];
        out[(size_t)NB * 64 + (size_t)(b0 + r) * NKG + k]     = grapes_scales[(b0 + r) * NKG + k];
        out[(size_t)NB * 64 + (size_t)(b0 + 8 + r) * NKG + k] = grapes_scales[(b0 + 8 + r) * NKG + k];
    } else if (tid < 224) {
        const int task = tid - 64;
        const int r = task / NKA, k = task % NKA;
        ai0 = aromas[(b0 + r) * NKA + k];
        ai1 = aromas[(b0 + 8 + r) * NKA + k];
        as0 = aromas_scales[(b0 + r) * NKA + k];
        as1 = aromas_scales[(b0 + 8 + r) * NKA + k];
        out[(size_t)NB * 92 + (size_t)(b0 + r) * NKA + k]     = as0;
        out[(size_t)NB * 92 + (size_t)(b0 + 8 + r) * NKA + k] = as1;
    }

#define FIN_HEADS(C, GB, ACC) do {                                              \
    float s_[4];                                                                \
    _Pragma("unroll")                                                           \
    for (int j = 0; j < 4; j++) {                                               \
        float lo, hi; UNPACK2(lo, hi, (ACC)[j]);                                \
        s_[j] = lo + hi;                                                        \
    }                                                                           \
    const int gb_ = (GB) + 4 * half;                                            \
    if ((C) < NNC) {                                                            \
        float bb = b_country[C];                                                \
        _Pragma("unroll")                                                       \
        for (int j = 0; j < 4; j++)                                             \
            out[(size_t)(gb_ + j) * NNC + (C)] = s_[j] + bb;                    \
    } else if ((C) == NNC) {                                                    \
        float bb = b_type[0];                                                   \
        _Pragma("unroll")                                                       \
        for (int j = 0; j < 4; j++)                                             \
            out[(size_t)NB * NNC + (gb_ + j)] = sigmoidf_(s_[j] + bb);          \
    } else if ((C) < 56) {                                                      \
        int cc_ = (C) - 51; float bb = b_taste[cc_];                            \
        _Pragma("unroll")                                                       \
        for (int j = 0; j < 4; j++)                                             \
            out[(size_t)NB * 51 + (size_t)(gb_ + j) * NNT + cc_] =              \
                sigmoidf_(s_[j] + bb);                                          \
    } else if ((C) < 88) {                                                      \
        int e_ = (C) - 56; float bb = b_grape[e_];                              \
        _Pragma("unroll")                                                       \
        for (int j = 0; j < 4; j++) yg_sm[(4 * half + j) * NE + e_] = s_[j] + bb; \
    } else if ((C) < 120) {                                                     \
        int e_ = (C) - 88; float bb = b_aroma[e_];                              \
        _Pragma("unroll")                                                       \
        for (int j = 0; j < 4; j++) ya_sm[(4 * half + j) * NE + e_] = s_[j] + bb; \
    } } while (0)

#define RAGGED(GB, GIDX, AIDX, ASC) do {                                        \
    if (tid < 64) {                                                             \
        const int r = tid >> 3, k = tid & 7;                                    \
        const int b = (GB) + r;                                                 \
        const float4* emb = reinterpret_cast<const float4*>(grapes_emb)         \
                          + (size_t)(GIDX) * (NE / 4);                          \
        const float4* yv4 = reinterpret_cast<const float4*>(&yg_sm[r * NE]);    \
        float a_ = 0.f;                                                         \
        _Pragma("unroll")                                                       \
        for (int i = 0; i < NE / 4; i++) {                                      \
            float4 ev = emb[i], yv = yv4[i];                                    \
            a_ += ev.x * yv.x + ev.y * yv.y + ev.z * yv.z + ev.w * yv.w;        \
        }                                                                       \
        float mask = ((GIDX) != 0) ? 1.f : 0.f;                                 \
        out[(size_t)NB * 56 + (size_t)b * NKG + k] = sigmoidf_(a_) * mask;      \
    } else if (tid < 224) {                                                     \
        const int task = tid - 64;                                              \
        const int r = task / NKA, k = task % NKA;                               \
        const int b = (GB) + r;                                                 \
        const float4* emb = reinterpret_cast<const float4*>(aroma_emb)          \
                          + (size_t)(AIDX) * (NE / 4);                          \
        const float4* yv4 = reinterpret_cast<const float4*>(&ya_sm[r * NE]);    \
        float a_ = 0.f;                                                         \
        _Pragma("unroll")                                                       \
        for (int i = 0; i < NE / 4; i++) {                                      \
            float4 ev = emb[i], yv = yv4[i];                                    \
            a_ += ev.x * yv.x + ev.y * yv.y + ev.z * yv.z + ev.w * yv.w;        \
        }                                                                       \
        float mask = ((ASC) != 0.f) ? 1.f : 0.f;                                \
        out[(size_t)NB * 72 + (size_t)b * NKA + k] = sigmoidf_(a_) * mask;      \
    } } while (0)

    // ================ P1: stream T0 cols [0,128) ================
    {
        const float4* p = x4 + (size_t)(b0 + sr) * SEQROW + sc;
        float4 m0 = p[0], m1 = p[64], m2 = p[128], m3 = p[192];
        #pragma unroll
        for (int s = 4; s < NS; s += 4) {
            float4 v0 = p[(s + 0) * 64], v1 = p[(s + 1) * 64];
            float4 v2 = p[(s + 2) * 64], v3 = p[(s + 3) * 64];
            FMAX4(m0, v0); FMAX4(m1, v1); FMAX4(m2, v2); FMAX4(m3, v3);
        }
        float4 rr;
        rr.x = fmaxf(fmaxf(m0.x, m1.x), fmaxf(m2.x, m3.x));
        rr.y = fmaxf(fmaxf(m0.y, m1.y), fmaxf(m2.y, m3.y));
        rr.z = fmaxf(fmaxf(m0.z, m1.z), fmaxf(m2.z, m3.z));
        rr.w = fmaxf(fmaxf(m0.w, m1.w), fmaxf(m2.w, m3.w));
        reinterpret_cast<float4*>(xs[0])[sr * (NY / 4) + sc] = rr;
    }
    __syncthreads();

    ull acc[4] = {0ull, 0ull, 0ull, 0ull};          // GEMM1(T0), live P2..P3
    const float* xb0 = &xs[0][4 * half * NY];

    // ===== P2: GEMM1(T0, K[0:128)) + stream T0 cols [128,256) =====
    {
        const float4* p = x4 + (size_t)(b0 + sr) * SEQROW + 32 + sc;
        float4 m0 = p[0], m1 = p[64];
        #pragma unroll 4
        for (int it = 0; it < 31; it++) {
            float4 v0 = p[(2 * it + 2) * 64];
            float4 v1 = p[(2 * it + 3) * 64];
            GSTEP(W_common, NH, h, xb0, NY, 4 * it, acc);
            FMAX4(m0, v0); FMAX4(m1, v1);
        }
        GSTEP(W_common, NH, h, xb0, NY, 124, acc);
        float4 rr;
        rr.x = fmaxf(m0.x, m1.x); rr.y = fmaxf(m0.y, m1.y);
        rr.z = fmaxf(m0.z, m1.z); rr.w = fmaxf(m0.w, m1.w);
        reinterpret_cast<float4*>(xs[0])[sr * (NY / 4) + 32 + sc] = rr;
    }
    __syncthreads();

    // ===== P3: GEMM1(T0, K[128:256)) + stream T1 cols [0,128); write ys(T0) =====
    {
        const float4* p = x4 + (size_t)(b0 + 8 + sr) * SEQROW + sc;
        float4 m0 = p[0], m1 = p[64];
        #pragma unroll 4
        for (int it = 0; it < 31; it++) {
            float4 v0 = p[(2 * it + 2) * 64];
            float4 v1 = p[(2 * it + 3) * 64];
            GSTEP(W_common, NH, h, xb0, NY, 128 + 4 * it, acc);
            FMAX4(m0, v0); FMAX4(m1, v1);
        }
        GSTEP(W_common, NH, h, xb0, NY, 252, acc);
        float4 rr;
        rr.x = fmaxf(m0.x, m1.x); rr.y = fmaxf(m0.y, m1.y);
        rr.z = fmaxf(m0.z, m1.z); rr.w = fmaxf(m0.w, m1.w);
        reinterpret_cast<float4*>(xs[1])[sr * (NY / 4) + sc] = rr;

        const float bcm = b_common[h];
        #pragma unroll
        for (int j = 0; j < 4; j++) {
            float lo, hi; UNPACK2(lo, hi, acc[j]);
            float v = lo + hi + bcm;
            ys[(4 * half + j) * NH + h] = (v > 0.f) ? v : expm1f(v);
        }
    }
    __syncthreads();

    // ===== P4: heads(T0) + stream T1 cols [128,256) =====
    {
        const float* ybase = &ys[4 * half * NH];
        ull acch[4] = {0ull, 0ull, 0ull, 0ull};
        const float4* p = x4 + (size_t)(b0 + 8 + sr) * SEQROW + 32 + sc;
        float4 m0 = p[0], m1 = p[64];
        #pragma unroll 4
        for (int it = 0; it < 31; it++) {
            float4 v0 = p[(2 * it + 2) * 64];
            float4 v1 = p[(2 * it + 3) * 64];
            GSTEP(Wp, hstride, hcc, ybase, NH, 4 * it, acch);
            FMAX4(m0, v0); FMAX4(m1, v1);
        }
        GSTEP(Wp, hstride, hcc, ybase, NH, 124, acch);
        float4 rr;
        rr.x = fmaxf(m0.x, m1.x); rr.y = fmaxf(m0.y, m1.y);
        rr.z = fmaxf(m0.z, m1.z); rr.w = fmaxf(m0.w, m1.w);
        reinterpret_cast<float4*>(xs[1])[sr * (NY / 4) + 32 + sc] = rr;

        FIN_HEADS(h, b0, acch);
    }
    __syncthreads();

    // ===== P5: ragged(T0) + GEMM1(T1, full K); write ys(T1) =====
    RAGGED(b0, gi0, ai0, as0);
    {
        ull acc2[4] = {0ull, 0ull, 0ull, 0ull};
        const float* xb1 = &xs[1][4 * half * NY];
        #pragma unroll 4
        for (int it = 0; it < 64; it++)
            GSTEP(W_common, NH, h, xb1, NY, 4 * it, acc2);
        const float bcm = b_common[h];
        #pragma unroll
        for (int j = 0; j < 4; j++) {
            float lo, hi; UNPACK2(lo, hi, acc2[j]);
            float v = lo + hi + bcm;
            ys[(4 * half + j) * NH + h] = (v > 0.f) ? v : expm1f(v);
        }
    }
    __syncthreads();

    // ===== P6: heads(T1) =====
    {
        const float* ybase = &ys[4 * half * NH];
        ull acch[4] = {0ull, 0ull, 0ull, 0ull};
        #pragma unroll 4
        for (int it = 0; it < 32; it++)
            GSTEP(Wp, hstride, hcc, ybase, NH, 4 * it, acch);
        FIN_HEADS(h, b0 + 8, acch);
    }
    __syncthreads();

    // ===== P7: ragged(T1) =====
    RAGGED(b0 + 8, gi1, ai1, as1);

#undef FIN_HEADS
#undef RAGGED
}

extern "C" void kernel_launch(void* const* d_in, const int* in_sizes, int n_in,
                              void* d_out, int out_size) {
    const float* x_enc          = (const float*)d_in[0];
    const int*   grapes         = (const int*)  d_in[1];
    const float* grapes_scales  = (const float*)d_in[2];
    const int*   aromas         = (const int*)  d_in[3];
    const float* aromas_scales  = (const float*)d_in[4];
    const float* W_common       = (const float*)d_in[5];
    const float* b_common       = (const float*)d_in[6];
    const float* W_country      = (const float*)d_in[7];
    const float* b_country      = (const float*)d_in[8];
    const float* W_type         = (const float*)d_in[9];
    const float* b_type         = (const float*)d_in[10];
    const float* W_taste        = (const float*)d_in[11];
    const float* b_taste        = (const float*)d_in[12];
    const float* W_aroma        = (const float*)d_in[13];
    const float* b_aroma        = (const float*)d_in[14];
    const float* W_grape        = (const float*)d_in[15];
    const float* b_grape        = (const float*)d_in[16];
    const float* grapes_emb     = (const float*)d_in[17];
    const float* aroma_emb      = (const float*)d_in[18];
    float* out = (float*)d_out;

    wine_p2<<<NB / 16, 256>>>(reinterpret_cast<const float4*>(x_enc),
                              grapes, grapes_scales, aromas, aromas_scales,
                              W_common, b_common, W_country, b_country,
                              W_type, b_type, W_taste, b_taste,
                              W_aroma, b_aroma, W_grape, b_grape,
                              grapes_emb, aroma_emb, out);
}